// round 16
// baseline (speedup 1.0000x reference)
#include <cuda_runtime.h>
#include <cuda_bf16.h>
#include <cstdint>

// Problem dims (fixed by the reference)
#define VOCAB 50000
#define EDIM  64
#define HDIM  64
#define BATCH 1024
#define SEQ   512
#define WPB   4            // warps per block
#define NBLK  128          // 128 blocks x 4 warps x 2 rows = 1024 rows exactly

// h line: j in [0,32) at float offset 0; j in [32,64) at offset 36 (16B pad
// shifts banks by 4 -> the two lane-group LDS.128 addresses are conflict-free)
#define HSTR  72

// Scratch: projected table proj[v][h] = b_ih[h]+b_hh[h] + sum_e emb[v,e]*W_ih[h,e]
__device__ float g_proj[VOCAB * HDIM];   // 12.8 MB, L2-resident in steady state
__device__ int   g_x64flag;              // 1 if token buffer is int64, 0 if int32

// Fast tanh: tanh(x) = 1 - 2/(1 + exp(2x)). ex2.approx + rcp.approx.
__device__ __forceinline__ float fast_tanh(float x) {
    float e, r;
    asm("ex2.approx.f32 %0, %1;" : "=f"(e) : "f"(x * 2.885390081777927f)); // 2/ln2
    asm("rcp.approx.f32 %0, %1;" : "=f"(r) : "f"(e + 1.0f));
    return fmaf(-2.0f, r, 1.0f);
}

#define FMA2(acc, a, b) asm("fma.rn.f32x2 %0, %1, %2, %0;" : "+l"(acc) : "l"(a), "l"(b))
#define ADD2(acc, b)    asm("add.rn.f32x2 %0, %0, %1;"     : "+l"(acc) : "l"(b))
#define PACK2F(d, lo, hi) asm("mov.b64 %0, {%1, %2};" : "=l"(d) : "f"(lo), "f"(hi))
#define UNPACK2(lo, hi, s) asm("mov.b64 {%0, %1}, %2;" : "=f"(lo), "=f"(hi) : "l"(s))

// ---------------------------------------------------------------------------
// Kernel A: build projected embedding table (fuses gather-side GEMM + biases).
// Block 0 warp 0 additionally detects int32-vs-int64 token layout.
// ---------------------------------------------------------------------------
#define PROJ_ROWS 32
__global__ __launch_bounds__(256) void proj_kernel(
    const int*   __restrict__ x32,
    const float* __restrict__ emb,
    const float* __restrict__ W_ih,
    const float* __restrict__ b_ih,
    const float* __restrict__ b_hh)
{
    __shared__ float s_w[HDIM * 65];
    __shared__ float s_e[PROJ_ROWS * EDIM];
    __shared__ float s_bias[HDIM];

    const int t  = threadIdx.x;
    const int v0 = blockIdx.x * PROJ_ROWS;

    if (blockIdx.x == 0 && t < 32) {
        unsigned m = __ballot_sync(0xffffffff, x32[2 * t + 1] != 0);
        if (t == 0) g_x64flag = (m == 0u) ? 1 : 0;
    }

    #pragma unroll
    for (int k = 0; k < 16; k++) {
        int idx = t + k * 256;
        int hg = idx >> 6, eg = idx & 63;
        s_w[hg * 65 + eg] = W_ih[idx];
    }
    #pragma unroll
    for (int k = 0; k < 8; k++) {
        int idx = t + k * 256;
        int r = idx >> 6, e = idx & 63;
        s_e[idx] = (v0 + r < VOCAB) ? emb[(long)(v0 + r) * EDIM + e] : 0.0f;
    }
    if (t < HDIM) s_bias[t] = b_ih[t] + b_hh[t];
    __syncthreads();

    const int h    = t & 63;
    const int rgrp = t >> 6;
    #pragma unroll
    for (int k = 0; k < 8; k++) {
        int r = rgrp + 4 * k;
        if (v0 + r >= VOCAB) break;
        float acc = s_bias[h];
        #pragma unroll
        for (int e = 0; e < EDIM; e++)
            acc += s_e[r * EDIM + e] * s_w[h * 65 + e];
        g_proj[(v0 + r) * HDIM + h] = acc;
    }
}

// ---------------------------------------------------------------------------
// Kernel B: TWO independent split-j fp32 chains per warp, shared weights.
// 128 blocks x 128 threads (1 warp/SMSP); each warp owns rows rA, rB.
// Split-j (validated R15): lane t covers j-half [0,32) if t<16 else [32,64),
// computing partials for its 2 outputs AND partner (t^16)'s 2 outputs over
// that half; shfl_xor(16) merges halves. 8 LDS.128 per row per step.
// The two rows' chains are data-independent -> row B's FFMA2s issue inside
// row A's LDS/shfl/tanh shadows (R6's ILP lever, minus R13's bf16+MIO taxes).
// Weights depend only on lane -> SHARED by both rows: 128 regs total.
// ---------------------------------------------------------------------------
__global__ __launch_bounds__(128, 1) void rnn_split2_kernel(
    const int*   __restrict__ x32,
    const float* __restrict__ W_hh,
    const float* __restrict__ fc_w,
    const float* __restrict__ fc_b,
    float*       __restrict__ out)
{
    __shared__ int   s_tok[WPB][2][SEQ];       // 16 KB [warp][row][t]
    __shared__ float s_h[WPB][2][2][HSTR];     // 4.6 KB [warp][row][buf][padded h]

    const int w    = threadIdx.x >> 5;         // warp in block: 0..3
    const int lane = threadIdx.x & 31;
    const int rA   = blockIdx.x * (WPB * 2) + w * 2;
    const int rB   = rA + 1;
    const int flag = g_x64flag;

    const int  lo    = (lane < 16);            // my j-half
    const int  jbase = lo ? 0 : 32;
    const int  hoff  = lo ? 0 : 36;            // 16B pad between halves
    const int  o0 = 2 * lane;                  // my outputs
    const int  q0 = 2 * (lane ^ 16);           // partner's outputs

    // Tokens for both rows (handles int32 or int64 source layout)
    for (int k = lane; k < SEQ; k += 32) {
        long a = (long)rA * SEQ + k;
        long b = (long)rB * SEQ + k;
        s_tok[w][0][k] = flag ? x32[2 * a] : x32[a];
        s_tok[w][1][k] = flag ? x32[2 * b] : x32[b];
    }
    __syncwarp();

    // Shared weights: 4 output-rows x my j-half, j-pair packed = 64 ull regs.
    unsigned long long wA[16], wB[16], wC[16], wD[16];
    {
        const ulonglong2* pa = (const ulonglong2*)(W_hh + (o0)     * HDIM + jbase);
        const ulonglong2* pb = (const ulonglong2*)(W_hh + (o0 + 1) * HDIM + jbase);
        const ulonglong2* pc = (const ulonglong2*)(W_hh + (q0)     * HDIM + jbase);
        const ulonglong2* pd = (const ulonglong2*)(W_hh + (q0 + 1) * HDIM + jbase);
        #pragma unroll
        for (int q = 0; q < 8; q++) {
            ulonglong2 a = pa[q]; wA[2 * q] = a.x; wA[2 * q + 1] = a.y;
            ulonglong2 b = pb[q]; wB[2 * q] = b.x; wB[2 * q + 1] = b.y;
            ulonglong2 c = pc[q]; wC[2 * q] = c.x; wC[2 * q + 1] = c.y;
            ulonglong2 d = pd[q]; wD[2 * q] = d.x; wD[2 * q + 1] = d.y;
        }
    }

    // h init
    *(float2*)&s_h[w][0][0][2 * lane + (lo ? 0 : 4)] = make_float2(0.0f, 0.0f);
    *(float2*)&s_h[w][1][0][2 * lane + (lo ? 0 : 4)] = make_float2(0.0f, 0.0f);
    __syncwarp();

    float hA0 = 0.0f, hA1 = 0.0f, hB0 = 0.0f, hB1 = 0.0f;

    // xp register pipelines, depth 3 per row
    float2 xA0 = *(const float2*)(g_proj + s_tok[w][0][0] * HDIM + o0);
    float2 xA1 = *(const float2*)(g_proj + s_tok[w][0][1] * HDIM + o0);
    float2 xA2 = *(const float2*)(g_proj + s_tok[w][0][2] * HDIM + o0);
    float2 xB0 = *(const float2*)(g_proj + s_tok[w][1][0] * HDIM + o0);
    float2 xB1 = *(const float2*)(g_proj + s_tok[w][1][1] * HDIM + o0);
    float2 xB2 = *(const float2*)(g_proj + s_tok[w][1][2] * HDIM + o0);

    #pragma unroll 2
    for (int t = 0; t < SEQ; t++) {
        const int cur = t & 1, nxt = cur ^ 1;
        const int tp = (t + 3 < SEQ) ? (t + 3) : (SEQ - 1);
        float2 xAf = *(const float2*)(g_proj + s_tok[w][0][tp] * HDIM + o0);
        float2 xBf = *(const float2*)(g_proj + s_tok[w][1][tp] * HDIM + o0);

        // Row A: 8 accs (depth-8 chains): (aA*,aB*) my outputs, (aC*,aD*) partner
        unsigned long long aA0 = 0, aA1 = 0, aB0 = 0, aB1 = 0;
        unsigned long long aC0 = 0, aC1 = 0, aD0 = 0, aD1 = 0;
        // Row B accumulators
        unsigned long long bA0 = 0, bA1 = 0, bB0 = 0, bB1 = 0;
        unsigned long long bC0 = 0, bC1 = 0, bD0 = 0, bD1 = 0;

        const float4* hpA = (const float4*)&s_h[w][0][cur][hoff];
        const float4* hpB = (const float4*)&s_h[w][1][cur][hoff];
        #pragma unroll
        for (int q = 0; q < 8; q++) {          // float4 = j-pairs 2q, 2q+1
            float4 uA = hpA[q];
            float4 uB = hpB[q];
            unsigned long long pA0, pA1, pB0, pB1;
            PACK2F(pA0, uA.x, uA.y);
            PACK2F(pA1, uA.z, uA.w);
            PACK2F(pB0, uB.x, uB.y);
            PACK2F(pB1, uB.z, uB.w);
            FMA2(aA0, pA0, wA[2 * q]); FMA2(aA1, pA1, wA[2 * q + 1]);
            FMA2(aB0, pA0, wB[2 * q]); FMA2(aB1, pA1, wB[2 * q + 1]);
            FMA2(aC0, pA0, wC[2 * q]); FMA2(aC1, pA1, wC[2 * q + 1]);
            FMA2(aD0, pA0, wD[2 * q]); FMA2(aD1, pA1, wD[2 * q + 1]);
            FMA2(bA0, pB0, wA[2 * q]); FMA2(bA1, pB1, wA[2 * q + 1]);
            FMA2(bB0, pB0, wB[2 * q]); FMA2(bB1, pB1, wB[2 * q + 1]);
            FMA2(bC0, pB0, wC[2 * q]); FMA2(bC1, pB1, wC[2 * q + 1]);
            FMA2(bD0, pB0, wD[2 * q]); FMA2(bD1, pB1, wD[2 * q + 1]);
        }
        ADD2(aA0, aA1); ADD2(aB0, aB1); ADD2(aC0, aC1); ADD2(aD0, aD1);
        ADD2(bA0, bA1); ADD2(bB0, bB1); ADD2(bC0, bC1); ADD2(bD0, bD1);

        float e, o;
        UNPACK2(e, o, aA0); float sAO0 = e + o;
        UNPACK2(e, o, aB0); float sAO1 = e + o;
        UNPACK2(e, o, aC0); float sAQ0 = e + o;
        UNPACK2(e, o, aD0); float sAQ1 = e + o;
        UNPACK2(e, o, bA0); float sBO0 = e + o;
        UNPACK2(e, o, bB0); float sBO1 = e + o;
        UNPACK2(e, o, bC0); float sBQ0 = e + o;
        UNPACK2(e, o, bD0); float sBQ1 = e + o;

        // Merge halves (partner's partials for MY outputs)
        float rA0 = __shfl_xor_sync(0xffffffffu, sAQ0, 16);
        float rA1 = __shfl_xor_sync(0xffffffffu, sAQ1, 16);
        float rB0 = __shfl_xor_sync(0xffffffffu, sBQ0, 16);
        float rB1 = __shfl_xor_sync(0xffffffffu, sBQ1, 16);

        hA0 = fast_tanh(xA0.x + sAO0 + rA0);
        hA1 = fast_tanh(xA0.y + sAO1 + rA1);
        hB0 = fast_tanh(xB0.x + sBO0 + rB0);
        hB1 = fast_tanh(xB0.y + sBO1 + rB1);

        *(float2*)&s_h[w][0][nxt][2 * lane + (lo ? 0 : 4)] = make_float2(hA0, hA1);
        *(float2*)&s_h[w][1][nxt][2 * lane + (lo ? 0 : 4)] = make_float2(hB0, hB1);
        __syncwarp();

        xA0 = xA1; xA1 = xA2; xA2 = xAf;
        xB0 = xB1; xB1 = xB2; xB2 = xBf;
    }

    // fc + sigmoid for both rows (fp32 register h, warp-local reduce)
    float2 f = *(const float2*)(fc_w + o0);
    float vA = hA0 * f.x + hA1 * f.y;
    float vB = hB0 * f.x + hB1 * f.y;
    #pragma unroll
    for (int off = 16; off; off >>= 1) {
        vA += __shfl_xor_sync(0xffffffffu, vA, off);
        vB += __shfl_xor_sync(0xffffffffu, vB, off);
    }
    if (lane == 0) {
        float bias = fc_b[0];
        out[rA] = 1.0f / (1.0f + expf(-(vA + bias)));
        out[rB] = 1.0f / (1.0f + expf(-(vB + bias)));
    }
}

// ---------------------------------------------------------------------------
// Launch. Inputs (metadata order): x, emb, W_ih, W_hh, b_ih, b_hh, fc_w, fc_b
// 2 launches/call so ncu -s 5 -c 1 lands on rnn_split2_kernel.
// ---------------------------------------------------------------------------
extern "C" void kernel_launch(void* const* d_in, const int* in_sizes, int n_in,
                              void* d_out, int out_size)
{
    const int*   x32  = (const int*)  d_in[0];
    const float* emb  = (const float*)d_in[1];
    const float* W_ih = (const float*)d_in[2];
    const float* W_hh = (const float*)d_in[3];
    const float* b_ih = (const float*)d_in[4];
    const float* b_hh = (const float*)d_in[5];
    const float* fc_w = (const float*)d_in[6];
    const float* fc_b = (const float*)d_in[7];
    float* out = (float*)d_out;

    proj_kernel<<<(VOCAB + PROJ_ROWS - 1) / PROJ_ROWS, 256>>>(x32, emb, W_ih, b_ih, b_hh);
    rnn_split2_kernel<<<NBLK, WPB * 32>>>(x32, W_hh, fc_w, fc_b, out);
}

// round 17
// speedup vs baseline: 1.0480x; 1.0480x over previous
#include <cuda_runtime.h>
#include <cuda_bf16.h>
#include <cstdint>

// Problem dims (fixed by the reference)
#define VOCAB 50000
#define EDIM  64
#define HDIM  64
#define BATCH 1024
#define SEQ   512
#define WPB   8            // warps per block
#define NBLK  128          // 128 x 8 = 1024 rows exactly; 2.0 warps/SMSP

// h line: j in [0,32) at float offset 0; j in [32,64) at offset 36 (16B pad
// -> the two lane-group LDS.128 address sets are bank-conflict-free)
#define HSTR  72

#define TANH_C 2.885390081777927f   // 2/ln2: e^{2a} = 2^{C*a}

// Scratch: projected table proj[v][h] = b_ih[h]+b_hh[h] + sum_e emb[v,e]*W_ih[h,e]
__device__ float g_proj[VOCAB * HDIM];   // 12.8 MB, L2-resident in steady state
__device__ int   g_x64flag;              // 1 if token buffer is int64, 0 if int32

#define FMA2(acc, a, b) asm("fma.rn.f32x2 %0, %1, %2, %0;" : "+l"(acc) : "l"(a), "l"(b))
#define ADD2(acc, b)    asm("add.rn.f32x2 %0, %0, %1;"     : "+l"(acc) : "l"(b))
#define PACK2F(d, lo, hi) asm("mov.b64 %0, {%1, %2};" : "=l"(d) : "f"(lo), "f"(hi))
#define UNPACK2(lo, hi, s) asm("mov.b64 {%0, %1}, %2;" : "=f"(lo), "=f"(hi) : "l"(s))
#define EX2(d, x)  asm("ex2.approx.f32 %0, %1;" : "=f"(d) : "f"(x))
#define RCP(d, x)  asm("rcp.approx.f32 %0, %1;" : "=f"(d) : "f"(x))

// ---------------------------------------------------------------------------
// Kernel A: build projected embedding table (fuses gather-side GEMM + biases).
// Block 0 warp 0 additionally detects int32-vs-int64 token layout.
// ---------------------------------------------------------------------------
#define PROJ_ROWS 32
__global__ __launch_bounds__(256) void proj_kernel(
    const int*   __restrict__ x32,
    const float* __restrict__ emb,
    const float* __restrict__ W_ih,
    const float* __restrict__ b_ih,
    const float* __restrict__ b_hh)
{
    __shared__ float s_w[HDIM * 65];
    __shared__ float s_e[PROJ_ROWS * EDIM];
    __shared__ float s_bias[HDIM];

    const int t  = threadIdx.x;
    const int v0 = blockIdx.x * PROJ_ROWS;

    if (blockIdx.x == 0 && t < 32) {
        unsigned m = __ballot_sync(0xffffffff, x32[2 * t + 1] != 0);
        if (t == 0) g_x64flag = (m == 0u) ? 1 : 0;
    }

    #pragma unroll
    for (int k = 0; k < 16; k++) {
        int idx = t + k * 256;
        int hg = idx >> 6, eg = idx & 63;
        s_w[hg * 65 + eg] = W_ih[idx];
    }
    #pragma unroll
    for (int k = 0; k < 8; k++) {
        int idx = t + k * 256;
        int r = idx >> 6, e = idx & 63;
        s_e[idx] = (v0 + r < VOCAB) ? emb[(long)(v0 + r) * EDIM + e] : 0.0f;
    }
    if (t < HDIM) s_bias[t] = b_ih[t] + b_hh[t];
    __syncthreads();

    const int h    = t & 63;
    const int rgrp = t >> 6;
    #pragma unroll
    for (int k = 0; k < 8; k++) {
        int r = rgrp + 4 * k;
        if (v0 + r >= VOCAB) break;
        float acc = s_bias[h];
        #pragma unroll
        for (int e = 0; e < EDIM; e++)
            acc += s_e[r * EDIM + e] * s_w[h * 65 + e];
        g_proj[(v0 + r) * HDIM + h] = acc;
    }
}

// ---------------------------------------------------------------------------
// Kernel B: split-j fp32 recurrence, r-form algebra, 2.0 warps/SMSP uniform.
// 128 blocks x 256 threads (8 warps) = 1024 rows exactly, 1 block/SM.
// Split-j (R15): lane t covers j-half [0,32) if t<16 else [32,64); computes
// partials for its 2 outputs and partner (t^16)'s 2; shfl_xor(16) merges.
// r-form: state stored in smem is r = 1/(1+e^{2a}), h = 1-2r. Weights are
// pre-scaled to -2W (exact) and per-output half-rowsums seed the accums, so
// Sum W*h = rowsum + Sum (-2W)*r emerges directly and the publish chain ends
// at the rcp (no trailing fmaf). C*xp carried pre-scaled in the prefetch
// pipeline; post-shfl chain = FMA -> ex2 -> FADD -> rcp -> STS (~45 cyc).
// ---------------------------------------------------------------------------
__global__ __launch_bounds__(256, 1) void rnn_rform_kernel(
    const int*   __restrict__ x32,
    const float* __restrict__ W_hh,
    const float* __restrict__ fc_w,
    const float* __restrict__ fc_b,
    float*       __restrict__ out)
{
    __shared__ int   s_tok[WPB][SEQ];          // 16 KB [warp][t]
    __shared__ float s_h[WPB][2][HSTR];        // 4.6 KB [warp][buf][padded r]

    const int w    = threadIdx.x >> 5;         // warp in block: 0..7
    const int lane = threadIdx.x & 31;
    const int row  = blockIdx.x * WPB + w;     // exact cover, no tail
    const int flag = g_x64flag;

    const int  lo    = (lane < 16);
    const int  jbase = lo ? 0 : 32;
    const int  hoff  = lo ? 0 : 36;
    const int  o0 = 2 * lane;                  // my outputs
    const int  q0 = 2 * (lane ^ 16);           // partner's outputs

    // Tokens (handles int32 or int64 source layout)
    for (int k = lane; k < SEQ; k += 32) {
        long base = (long)row * SEQ + k;
        s_tok[w][k] = flag ? x32[2 * base] : x32[base];
    }
    __syncwarp();

    // Weights: 4 output-rows x my j-half, scaled to -2W, j-pair packed
    // (64 ull regs); plus 4 half-rowsums of the RAW W.
    unsigned long long wA[16], wB[16], wC[16], wD[16];
    float rsA = 0.0f, rsB = 0.0f, rsC = 0.0f, rsD = 0.0f;
    {
        const float4* pa = (const float4*)(W_hh + (o0)     * HDIM + jbase);
        const float4* pb = (const float4*)(W_hh + (o0 + 1) * HDIM + jbase);
        const float4* pc = (const float4*)(W_hh + (q0)     * HDIM + jbase);
        const float4* pd = (const float4*)(W_hh + (q0 + 1) * HDIM + jbase);
        #pragma unroll
        for (int q = 0; q < 8; q++) {
            float4 a = pa[q];
            rsA += (a.x + a.y) + (a.z + a.w);
            PACK2F(wA[2 * q],     -2.0f * a.x, -2.0f * a.y);
            PACK2F(wA[2 * q + 1], -2.0f * a.z, -2.0f * a.w);
            float4 b = pb[q];
            rsB += (b.x + b.y) + (b.z + b.w);
            PACK2F(wB[2 * q],     -2.0f * b.x, -2.0f * b.y);
            PACK2F(wB[2 * q + 1], -2.0f * b.z, -2.0f * b.w);
            float4 c = pc[q];
            rsC += (c.x + c.y) + (c.z + c.w);
            PACK2F(wC[2 * q],     -2.0f * c.x, -2.0f * c.y);
            PACK2F(wC[2 * q + 1], -2.0f * c.z, -2.0f * c.w);
            float4 d = pd[q];
            rsD += (d.x + d.y) + (d.z + d.w);
            PACK2F(wD[2 * q],     -2.0f * d.x, -2.0f * d.y);
            PACK2F(wD[2 * q + 1], -2.0f * d.z, -2.0f * d.w);
        }
    }

    // r init: h=0 <=> r=0.5
    *(float2*)&s_h[w][0][2 * lane + (lo ? 0 : 4)] = make_float2(0.5f, 0.5f);
    __syncwarp();

    // Prefetch pipeline carries C*xp (xp only ever used scaled), depth 3
    float2 cx0, cx1, cx2;
    {
        float2 a = *(const float2*)(g_proj + s_tok[w][0] * HDIM + o0);
        float2 b = *(const float2*)(g_proj + s_tok[w][1] * HDIM + o0);
        float2 c = *(const float2*)(g_proj + s_tok[w][2] * HDIM + o0);
        cx0 = make_float2(TANH_C * a.x, TANH_C * a.y);
        cx1 = make_float2(TANH_C * b.x, TANH_C * b.y);
        cx2 = make_float2(TANH_C * c.x, TANH_C * c.y);
    }

    float rr0 = 0.5f, rr1 = 0.5f;              // loop-carried r for fc

    #pragma unroll 2
    for (int t = 0; t < SEQ; t++) {
        const int cur = t & 1, nxt = cur ^ 1;
        const int tp = (t + 3 < SEQ) ? (t + 3) : (SEQ - 1);
        float2 xf = *(const float2*)(g_proj + s_tok[w][tp] * HDIM + o0);

        // Accumulators seeded with half-rowsums (depth-8 chains)
        unsigned long long aA0, aA1 = 0, aB0, aB1 = 0;
        unsigned long long aC0, aC1 = 0, aD0, aD1 = 0;
        PACK2F(aA0, rsA, 0.0f);
        PACK2F(aB0, rsB, 0.0f);
        PACK2F(aC0, rsC, 0.0f);
        PACK2F(aD0, rsD, 0.0f);

        // 8 LDS.128 over my j-half of the r line
        const float4* hp = (const float4*)&s_h[w][cur][hoff];
        #pragma unroll
        for (int q = 0; q < 8; q++) {
            float4 u = hp[q];
            unsigned long long p0, p1;
            PACK2F(p0, u.x, u.y);
            PACK2F(p1, u.z, u.w);
            FMA2(aA0, p0, wA[2 * q]); FMA2(aA1, p1, wA[2 * q + 1]);
            FMA2(aB0, p0, wB[2 * q]); FMA2(aB1, p1, wB[2 * q + 1]);
            FMA2(aC0, p0, wC[2 * q]); FMA2(aC1, p1, wC[2 * q + 1]);
            FMA2(aD0, p0, wD[2 * q]); FMA2(aD1, p1, wD[2 * q + 1]);
        }
        ADD2(aA0, aA1); ADD2(aB0, aB1); ADD2(aC0, aC1); ADD2(aD0, aD1);

        float e, o;
        UNPACK2(e, o, aA0); float sO0 = e + o;   // my outputs, my half (incl rowsum)
        UNPACK2(e, o, aB0); float sO1 = e + o;
        UNPACK2(e, o, aC0); float sQ0 = e + o;   // partner outputs, my half
        UNPACK2(e, o, aD0); float sQ1 = e + o;

        // shfl (26 cyc) runs in parallel with the u-path fma below
        float r0 = __shfl_xor_sync(0xffffffffu, sQ0, 16);
        float r1 = __shfl_xor_sync(0xffffffffu, sQ1, 16);
        float u0 = fmaf(TANH_C, sO0, cx0.x);
        float u1 = fmaf(TANH_C, sO1, cx0.y);

        // post-shfl: FMA -> ex2 -> FADD -> rcp -> STS
        float a0 = fmaf(TANH_C, r0, u0);
        float a1 = fmaf(TANH_C, r1, u1);
        float e0, e1;
        EX2(e0, a0);
        EX2(e1, a1);
        RCP(rr0, e0 + 1.0f);
        RCP(rr1, e1 + 1.0f);

        *(float2*)&s_h[w][nxt][2 * lane + (lo ? 0 : 4)] = make_float2(rr0, rr1);
        __syncwarp();

        cx0 = cx1; cx1 = cx2;
        cx2 = make_float2(TANH_C * xf.x, TANH_C * xf.y);
    }

    // fc + sigmoid: h = 1 - 2r (exact affine), warp-local reduce
    float h0 = fmaf(-2.0f, rr0, 1.0f);
    float h1 = fmaf(-2.0f, rr1, 1.0f);
    float2 f = *(const float2*)(fc_w + o0);
    float v = h0 * f.x + h1 * f.y;
    #pragma unroll
    for (int off = 16; off; off >>= 1)
        v += __shfl_xor_sync(0xffffffffu, v, off);
    if (lane == 0)
        out[row] = 1.0f / (1.0f + expf(-(v + fc_b[0])));
}

// ---------------------------------------------------------------------------
// Launch. Inputs (metadata order): x, emb, W_ih, W_hh, b_ih, b_hh, fc_w, fc_b
// 2 launches/call so ncu -s 5 -c 1 lands on rnn_rform_kernel.
// ---------------------------------------------------------------------------
extern "C" void kernel_launch(void* const* d_in, const int* in_sizes, int n_in,
                              void* d_out, int out_size)
{
    const int*   x32  = (const int*)  d_in[0];
    const float* emb  = (const float*)d_in[1];
    const float* W_ih = (const float*)d_in[2];
    const float* W_hh = (const float*)d_in[3];
    const float* b_ih = (const float*)d_in[4];
    const float* b_hh = (const float*)d_in[5];
    const float* fc_w = (const float*)d_in[6];
    const float* fc_b = (const float*)d_in[7];
    float* out = (float*)d_out;

    proj_kernel<<<(VOCAB + PROJ_ROWS - 1) / PROJ_ROWS, 256>>>(x32, emb, W_ih, b_ih, b_hh);
    rnn_rform_kernel<<<NBLK, WPB * 32>>>(x32, W_hh, fc_w, fc_b, out);
}